// round 6
// baseline (speedup 1.0000x reference)
#include <cuda_runtime.h>

#define BB 16
#define DD 32
#define CC 768
#define NHH 8
#define NOO 24
#define HWG 64
#define NPAIR (NHH*NOO)   // 192
#define H1 512
#define H2 256
#define H3 117
#define MT 24             // pair rows per block in MLP kernel (192*16/24 = 128 blocks)
#define YSPLIT 4

// Scratch (device globals -- allocation-free)
__device__ float g_part[BB*DD*YSPLIT*CC];   // 6.3 MB pooling partials
__device__ float g_invcnt[BB*DD];
__device__ float g_U[BB*DD*H1];             // 1 MB
__device__ int   g_hrow[BB*NHH];
__device__ int   g_orow[BB*NOO];

// ---------------------------------------------------------------------------
// Packed fp32x2 helpers (sm_103a FFMA2 -- PTX-only)
// ---------------------------------------------------------------------------
__device__ __forceinline__ void fma2(unsigned long long& d,
                                     unsigned long long a,
                                     unsigned long long b) {
    asm("fma.rn.f32x2 %0, %1, %2, %0;" : "+l"(d) : "l"(a), "l"(b));
}
__device__ __forceinline__ unsigned long long bcast2(float v) {
    unsigned long long r;
    asm("mov.b64 %0, {%1, %1};" : "=l"(r) : "r"(__float_as_uint(v)));
    return r;
}
__device__ __forceinline__ float2 unpack2(unsigned long long v) {
    unsigned lo, hi;
    asm("mov.b64 {%0, %1}, %2;" : "=r"(lo), "=r"(hi) : "l"(v));
    return make_float2(__uint_as_float(lo), __uint_as_float(hi));
}

// ---------------------------------------------------------------------------
// Kernel 1: ROI pooling partials (grid 2048 = bd*4 y-interleaved sub-blocks)
//           + sort absorbed into one extra block (blockIdx == 2048).
// ---------------------------------------------------------------------------
__global__ __launch_bounds__(192) void pool_kernel(
    const float* __restrict__ feat, const float* __restrict__ boxes,
    const float* __restrict__ scores)
{
    int blk = blockIdx.x;
    if (blk == BB * DD * YSPLIT) {
        // ---- sort block: per-batch stable descending ranks ----
        __shared__ float s[BB*DD];
        int t = threadIdx.x;
        for (int e = t; e < BB*DD; e += 192) s[e] = scores[e];
        __syncthreads();
        for (int e = t; e < BB*DD; e += 192) {
            int b = e >> 5, d = e & 31;
            float v = s[e];
            if (d < NHH) {
                int r = 0;
                for (int j = 0; j < NHH; ++j) {
                    float u = s[b*32 + j];
                    r += (u > v) || (u == v && j < d);
                }
                g_hrow[b*NHH + r] = e;
            } else {
                int r = 0;
                for (int j = NHH; j < DD; ++j) {
                    float u = s[b*32 + j];
                    r += (u > v) || (u == v && j < d);
                }
                g_orow[b*NOO + r] = e;
            }
        }
        return;
    }

    int bd = blk >> 2;              // 0..511
    int z  = blk & 3;               // y sub-slice
    int b  = bd >> 5;
    const float* box = boxes + bd * 4;
    float cx = box[0], cy = box[1], bw = box[2], bh = box[3];
    float hwd = __fmul_rn(bw, 0.5f);
    float hht = __fmul_rn(bh, 0.5f);
    int x1 = (int)floorf(__fdiv_rn(__fmul_rn(__fsub_rn(cx, hwd), 896.0f), 14.0f));
    int y1 = (int)floorf(__fdiv_rn(__fmul_rn(__fsub_rn(cy, hht), 896.0f), 14.0f));
    int x2 = (int)floorf(__fdiv_rn(__fmul_rn(__fadd_rn(cx, hwd), 896.0f), 14.0f));
    int y2 = (int)floorf(__fdiv_rn(__fmul_rn(__fadd_rn(cy, hht), 896.0f), 14.0f));
    x1 = max(x1, 0); y1 = max(y1, 0);
    x2 = min(x2, HWG); y2 = min(y2, HWG);
    int nx = max(x2 - x1, 0), ny = max(y2 - y1, 0);

    int t = threadIdx.x;            // channel float4 lane
    const float4* f4 = (const float4*)feat;
    // Four independent accumulator streams -> 4 LDG.128 in flight per warp
    float4 a0 = make_float4(0.f,0.f,0.f,0.f);
    float4 a1 = make_float4(0.f,0.f,0.f,0.f);
    float4 a2 = make_float4(0.f,0.f,0.f,0.f);
    float4 a3 = make_float4(0.f,0.f,0.f,0.f);
    const int S = CC / 4;
    for (int y = y1 + z; y < y2; y += YSPLIT) {
        int base = ((b * HWG + y) * HWG + x1) * S + t;
        int x = 0;
        for (; x + 4 <= nx; x += 4, base += 4 * S) {
            float4 v0 = __ldg(&f4[base]);
            float4 v1 = __ldg(&f4[base + S]);
            float4 v2 = __ldg(&f4[base + 2*S]);
            float4 v3 = __ldg(&f4[base + 3*S]);
            a0.x += v0.x; a0.y += v0.y; a0.z += v0.z; a0.w += v0.w;
            a1.x += v1.x; a1.y += v1.y; a1.z += v1.z; a1.w += v1.w;
            a2.x += v2.x; a2.y += v2.y; a2.z += v2.z; a2.w += v2.w;
            a3.x += v3.x; a3.y += v3.y; a3.z += v3.z; a3.w += v3.w;
        }
        for (; x < nx; ++x, base += S) {
            float4 v0 = __ldg(&f4[base]);
            a0.x += v0.x; a0.y += v0.y; a0.z += v0.z; a0.w += v0.w;
        }
    }
    a0.x += a1.x + a2.x + a3.x;
    a0.y += a1.y + a2.y + a3.y;
    a0.z += a1.z + a2.z + a3.z;
    a0.w += a1.w + a2.w + a3.w;
    ((float4*)g_part)[(bd * YSPLIT + z) * S + t] = a0;
    if (z == 0 && t == 0)
        g_invcnt[bd] = 1.0f / (float)(nx * ny);
}

// ---------------------------------------------------------------------------
// Kernel 2: U = pooled @ w1_half. Grid (64, 4), 256 threads.
// Split-K halves + smem reduce; 16-k double-buffered weight registers.
// ---------------------------------------------------------------------------
__global__ __launch_bounds__(256) void gemm1_kernel(const float* __restrict__ w1)
{
    __shared__ float As[CC * 8];       // 24 KB, [k][r]
    __shared__ float red[128 * 8];     // 4 KB split-K partials
    int r0 = blockIdx.x * 8;
    int t = threadIdx.x;

    for (int idx = t; idx < 8 * CC; idx += 256) {
        int r = idx / CC, k = idx - r * CC;
        int bd = r0 + r;
        const float* p = g_part + (bd * YSPLIT) * CC + k;
        float v = (p[0] + p[CC] + p[2*CC] + p[3*CC]) * __ldg(&g_invcnt[bd]);
        As[k * 8 + r] = v;
    }
    __syncthreads();

    int half = t >> 7;                 // 0/1
    int lt   = t & 127;
    int col  = blockIdx.y * 128 + lt;
    int off  = ((r0 & 31) < NHH) ? 0 : CC;
    const float* wp = w1 + off * H1 + col;
    int kb = half * (CC / 2);          // 0 or 384

    unsigned long long acc[4];
#pragma unroll
    for (int p = 0; p < 4; ++p) acc[p] = 0ULL;

    float wcur[16];
#pragma unroll
    for (int i = 0; i < 16; ++i) wcur[i] = __ldg(&wp[(kb + i) * H1]);

    for (int k0 = kb; k0 < kb + CC/2; k0 += 16) {
        float wnxt[16];
        int kn = (k0 + 16 < kb + CC/2) ? (k0 + 16) : kb;
#pragma unroll
        for (int i = 0; i < 16; ++i) wnxt[i] = __ldg(&wp[(kn + i) * H1]);
#pragma unroll
        for (int i = 0; i < 16; ++i) {
            unsigned long long wpk = bcast2(wcur[i]);
            const ulonglong2* ap = (const ulonglong2*)&As[(k0 + i) * 8];
            ulonglong2 q0 = ap[0], q1 = ap[1];
            fma2(acc[0], q0.x, wpk); fma2(acc[1], q0.y, wpk);
            fma2(acc[2], q1.x, wpk); fma2(acc[3], q1.y, wpk);
        }
#pragma unroll
        for (int i = 0; i < 16; ++i) wcur[i] = wnxt[i];
    }

    if (half == 1) {
#pragma unroll
        for (int p = 0; p < 4; ++p) {
            float2 f = unpack2(acc[p]);
            red[lt * 8 + 2*p]     = f.x;
            red[lt * 8 + 2*p + 1] = f.y;
        }
    }
    __syncthreads();
    if (half == 0) {
#pragma unroll
        for (int p = 0; p < 4; ++p) {
            float2 f = unpack2(acc[p]);
            g_U[(r0 + 2*p)     * H1 + col] = f.x + red[lt * 8 + 2*p];
            g_U[(r0 + 2*p + 1) * H1 + col] = f.y + red[lt * 8 + 2*p + 1];
        }
    }
}

// ---------------------------------------------------------------------------
// Kernel 3: fused pair-build + relu(x1) + GEMM2 + relu + GEMM3 + bias.
// 128 blocks of MT=24 pairs (single wave), 256 threads.
// x1 is built in 4 chunks of 128 k (12 KB buffer) interleaved with GEMM2.
// ---------------------------------------------------------------------------
__global__ __launch_bounds__(256) void pair_mlp_kernel(
    const float* __restrict__ b1,
    const float* __restrict__ w2, const float* __restrict__ b2,
    const float* __restrict__ w3, const float* __restrict__ b3,
    float* __restrict__ out)
{
    __shared__ float x1c[128 * MT];  // 12 KB chunk, [k_local][m] (reused phase-3)
    __shared__ float x2t[H2 * MT];   // 24 KB, [k][m]
    __shared__ int hr[MT], orr[MT];

    int g0 = blockIdx.x * MT;
    int t = threadIdx.x;

    if (t < MT) {
        int g = g0 + t;
        int b = g / NPAIR;
        int rem = g - b * NPAIR;
        int i = rem / NOO, j = rem - i * NOO;
        hr[t]  = g_hrow[b * NHH + i];
        orr[t] = g_orow[b * NOO + j];
    }
    __syncthreads();

    // -------- GEMM2 with chunked x1 build --------
    const float* wp = w2 + t;
    unsigned long long acc[12];
#pragma unroll
    for (int p = 0; p < 12; ++p) acc[p] = 0ULL;

    for (int kc = 0; kc < H1; kc += 128) {
        // build chunk: x1c[kl][m] = relu(U[hr][kc+kl] + U[orr][kc+kl] + b1)
        for (int idx = t; idx < MT * 32; idx += 256) {
            int n4 = idx / MT, m = idx - n4 * MT;
            int n = kc + n4 * 4;
            float4 uh = __ldg((const float4*)&g_U[hr[m]  * H1 + n]);
            float4 uo = __ldg((const float4*)&g_U[orr[m] * H1 + n]);
            float4 bb = __ldg((const float4*)&b1[n]);
            x1c[(n4*4+0) * MT + m] = fmaxf(uh.x + uo.x + bb.x, 0.f);
            x1c[(n4*4+1) * MT + m] = fmaxf(uh.y + uo.y + bb.y, 0.f);
            x1c[(n4*4+2) * MT + m] = fmaxf(uh.z + uo.z + bb.z, 0.f);
            x1c[(n4*4+3) * MT + m] = fmaxf(uh.w + uo.w + bb.w, 0.f);
        }
        __syncthreads();

        float wcur[16];
#pragma unroll
        for (int i = 0; i < 16; ++i) wcur[i] = __ldg(&wp[(kc + i) * H2]);

        for (int k0 = 0; k0 < 128; k0 += 16) {
            float wnxt[16];
            int kn = (k0 + 16 < 128) ? (kc + k0 + 16) : kc;
#pragma unroll
            for (int i = 0; i < 16; ++i) wnxt[i] = __ldg(&wp[(kn + i) * H2]);
#pragma unroll
            for (int i = 0; i < 16; ++i) {
                unsigned long long wpk = bcast2(wcur[i]);
                const ulonglong2* ap = (const ulonglong2*)&x1c[(k0 + i) * MT];
                ulonglong2 q0 = ap[0], q1 = ap[1], q2 = ap[2];
                ulonglong2 q3 = ap[3], q4 = ap[4], q5 = ap[5];
                fma2(acc[0],  q0.x, wpk); fma2(acc[1],  q0.y, wpk);
                fma2(acc[2],  q1.x, wpk); fma2(acc[3],  q1.y, wpk);
                fma2(acc[4],  q2.x, wpk); fma2(acc[5],  q2.y, wpk);
                fma2(acc[6],  q3.x, wpk); fma2(acc[7],  q3.y, wpk);
                fma2(acc[8],  q4.x, wpk); fma2(acc[9],  q4.y, wpk);
                fma2(acc[10], q5.x, wpk); fma2(acc[11], q5.y, wpk);
            }
#pragma unroll
            for (int i = 0; i < 16; ++i) wcur[i] = wnxt[i];
        }
        __syncthreads();
    }
    {
        float bb = __ldg(&b2[t]);
#pragma unroll
        for (int p = 0; p < 12; ++p) {
            float2 f = unpack2(acc[p]);
            float2 s;
            s.x = fmaxf(f.x + bb, 0.f);
            s.y = fmaxf(f.y + bb, 0.f);
            *(float2*)&x2t[t * MT + 2*p] = s;
        }
    }
    __syncthreads();

    // -------- GEMM3: out = x2 @ w3 + b3. 234 threads, split-K halves. --------
    float a3[MT];
    int half = (t >= H3) ? 1 : 0;
    int col  = t - half * H3;
    if (t < 2 * H3) {
        unsigned long long acc3[12];
#pragma unroll
        for (int p = 0; p < 12; ++p) acc3[p] = 0ULL;
        const float* wp3 = w3 + col;
        int kbeg = half * (H2/2);

        float wcur[16];
#pragma unroll
        for (int i = 0; i < 16; ++i) wcur[i] = __ldg(&wp3[(kbeg + i) * H3]);

        for (int k0 = kbeg; k0 < kbeg + H2/2; k0 += 16) {
            float wnxt[16];
            int kn = (k0 + 16 < kbeg + H2/2) ? (k0 + 16) : kbeg;
#pragma unroll
            for (int i = 0; i < 16; ++i) wnxt[i] = __ldg(&wp3[(kn + i) * H3]);
#pragma unroll
            for (int i = 0; i < 16; ++i) {
                unsigned long long wpk = bcast2(wcur[i]);
                const ulonglong2* ap = (const ulonglong2*)&x2t[(k0 + i) * MT];
                ulonglong2 q0 = ap[0], q1 = ap[1], q2 = ap[2];
                ulonglong2 q3 = ap[3], q4 = ap[4], q5 = ap[5];
                fma2(acc3[0],  q0.x, wpk); fma2(acc3[1],  q0.y, wpk);
                fma2(acc3[2],  q1.x, wpk); fma2(acc3[3],  q1.y, wpk);
                fma2(acc3[4],  q2.x, wpk); fma2(acc3[5],  q2.y, wpk);
                fma2(acc3[6],  q3.x, wpk); fma2(acc3[7],  q3.y, wpk);
                fma2(acc3[8],  q4.x, wpk); fma2(acc3[9],  q4.y, wpk);
                fma2(acc3[10], q5.x, wpk); fma2(acc3[11], q5.y, wpk);
            }
#pragma unroll
            for (int i = 0; i < 16; ++i) wcur[i] = wnxt[i];
        }
#pragma unroll
        for (int p = 0; p < 12; ++p) {
            float2 f = unpack2(acc3[p]);
            a3[2*p] = f.x; a3[2*p + 1] = f.y;
        }
        if (half == 1) {
#pragma unroll
            for (int m = 0; m < MT; ++m) x1c[col * MT + m] = a3[m];
        }
    }
    __syncthreads();
    if (t < H3) {
        float bo = __ldg(&b3[t]);
#pragma unroll
        for (int m = 0; m < MT; ++m)
            out[(g0 + m) * H3 + t] = a3[m] + x1c[t * MT + m] + bo;
    }
}

// ---------------------------------------------------------------------------
extern "C" void kernel_launch(void* const* d_in, const int* in_sizes, int n_in,
                              void* d_out, int out_size)
{
    const float* features = (const float*)d_in[0];
    const float* boxes    = (const float*)d_in[1];
    const float* scores   = (const float*)d_in[2];
    const float* w1       = (const float*)d_in[3];
    const float* b1       = (const float*)d_in[4];
    const float* w2       = (const float*)d_in[5];
    const float* b2       = (const float*)d_in[6];
    const float* w3       = (const float*)d_in[7];
    const float* b3       = (const float*)d_in[8];
    float* out = (float*)d_out;

    pool_kernel<<<BB * DD * YSPLIT + 1, 192>>>(features, boxes, scores);
    dim3 g1(BB * DD / 8, H1 / 128);
    gemm1_kernel<<<g1, 256>>>(w1);
    pair_mlp_kernel<<<(BB * NPAIR) / MT, 256>>>(b1, w2, b2, w3, b3, out);
}

// round 7
// speedup vs baseline: 1.0861x; 1.0861x over previous
#include <cuda_runtime.h>

#define BB 16
#define DD 32
#define CC 768
#define NHH 8
#define NOO 24
#define HWG 64
#define NPAIR (NHH*NOO)   // 192
#define H1 512
#define H2 256
#define H3 117
#define MT 12             // pair rows per block in MLP kernel
#define YSPLIT 8

// Scratch (device globals -- allocation-free)
__device__ float g_part[BB*DD*YSPLIT*CC];   // 50 MB pooling partials
__device__ float g_pooled[BB*DD*CC];        // 1.5 MB
__device__ float g_invcnt[BB*DD];
__device__ float g_U[BB*DD*H1];             // 1 MB
__device__ int   g_hrow[BB*NHH];
__device__ int   g_orow[BB*NOO];

// ---------------------------------------------------------------------------
// Packed fp32x2 helpers (sm_103a FFMA2 -- PTX-only)
// ---------------------------------------------------------------------------
__device__ __forceinline__ void fma2(unsigned long long& d,
                                     unsigned long long a,
                                     unsigned long long b) {
    asm("fma.rn.f32x2 %0, %1, %2, %0;" : "+l"(d) : "l"(a), "l"(b));
}
__device__ __forceinline__ unsigned long long bcast2(float v) {
    unsigned long long r;
    asm("mov.b64 %0, {%1, %1};" : "=l"(r) : "r"(__float_as_uint(v)));
    return r;
}
__device__ __forceinline__ float2 unpack2(unsigned long long v) {
    unsigned lo, hi;
    asm("mov.b64 {%0, %1}, %2;" : "=r"(lo), "=r"(hi) : "l"(v));
    return make_float2(__uint_as_float(lo), __uint_as_float(hi));
}

// ---------------------------------------------------------------------------
// Kernel 1: ROI pooling partials (grid 4096 = bd*8 y-interleaved sub-blocks)
//           + sort absorbed into one extra block (blockIdx == 4096).
// ---------------------------------------------------------------------------
__global__ __launch_bounds__(192) void pool_kernel(
    const float* __restrict__ feat, const float* __restrict__ boxes,
    const float* __restrict__ scores)
{
    int blk = blockIdx.x;
    if (blk == BB * DD * YSPLIT) {
        // ---- sort block: per-batch stable descending ranks ----
        __shared__ float s[BB*DD];
        int t = threadIdx.x;
        for (int e = t; e < BB*DD; e += 192) s[e] = scores[e];
        __syncthreads();
        for (int e = t; e < BB*DD; e += 192) {
            int b = e >> 5, d = e & 31;
            float v = s[e];
            if (d < NHH) {
                int r = 0;
                for (int j = 0; j < NHH; ++j) {
                    float u = s[b*32 + j];
                    r += (u > v) || (u == v && j < d);
                }
                g_hrow[b*NHH + r] = e;
            } else {
                int r = 0;
                for (int j = NHH; j < DD; ++j) {
                    float u = s[b*32 + j];
                    r += (u > v) || (u == v && j < d);
                }
                g_orow[b*NOO + r] = e;
            }
        }
        return;
    }

    int bd = blk >> 3;              // 0..511
    int z  = blk & 7;               // y sub-slice
    int b  = bd >> 5;
    const float* box = boxes + bd * 4;
    float cx = box[0], cy = box[1], bw = box[2], bh = box[3];
    float hwd = __fmul_rn(bw, 0.5f);
    float hht = __fmul_rn(bh, 0.5f);
    int x1 = (int)floorf(__fdiv_rn(__fmul_rn(__fsub_rn(cx, hwd), 896.0f), 14.0f));
    int y1 = (int)floorf(__fdiv_rn(__fmul_rn(__fsub_rn(cy, hht), 896.0f), 14.0f));
    int x2 = (int)floorf(__fdiv_rn(__fmul_rn(__fadd_rn(cx, hwd), 896.0f), 14.0f));
    int y2 = (int)floorf(__fdiv_rn(__fmul_rn(__fadd_rn(cy, hht), 896.0f), 14.0f));
    x1 = max(x1, 0); y1 = max(y1, 0);
    x2 = min(x2, HWG); y2 = min(y2, HWG);
    int nx = max(x2 - x1, 0), ny = max(y2 - y1, 0);

    int t = threadIdx.x;            // channel float4 lane
    const float4* f4 = (const float4*)feat;
    const int S = CC / 4;
    float4 acc0 = make_float4(0.f, 0.f, 0.f, 0.f);
    float4 acc1 = make_float4(0.f, 0.f, 0.f, 0.f);
    for (int y = y1 + z; y < y2; y += YSPLIT) {
        int base = ((b * HWG + y) * HWG + x1) * S + t;
        int x = 0;
#pragma unroll 2
        for (; x + 2 <= nx; x += 2, base += 2 * S) {
            float4 v0 = __ldg(&f4[base]);
            float4 v1 = __ldg(&f4[base + S]);
            acc0.x += v0.x; acc0.y += v0.y; acc0.z += v0.z; acc0.w += v0.w;
            acc1.x += v1.x; acc1.y += v1.y; acc1.z += v1.z; acc1.w += v1.w;
        }
        if (x < nx) {
            float4 v0 = __ldg(&f4[base]);
            acc0.x += v0.x; acc0.y += v0.y; acc0.z += v0.z; acc0.w += v0.w;
        }
    }
    acc0.x += acc1.x; acc0.y += acc1.y; acc0.z += acc1.z; acc0.w += acc1.w;
    ((float4*)g_part)[(bd * YSPLIT + z) * S + t] = acc0;
    if (z == 0 && t == 0)
        g_invcnt[bd] = 1.0f / (float)(nx * ny);
}

// ---------------------------------------------------------------------------
// Kernel 1b: collapse partials -> g_pooled (mean). 512 blocks, 192 threads.
// ---------------------------------------------------------------------------
__global__ __launch_bounds__(192) void reduce_kernel()
{
    int bd = blockIdx.x;
    int t = threadIdx.x;
    const int S = CC / 4;
    const float4* p = ((const float4*)g_part) + (bd * YSPLIT) * S + t;
    float4 s0 = p[0], s1 = p[S];
#pragma unroll
    for (int z = 2; z < YSPLIT; z += 2) {
        float4 v0 = p[z * S], v1 = p[(z+1) * S];
        s0.x += v0.x; s0.y += v0.y; s0.z += v0.z; s0.w += v0.w;
        s1.x += v1.x; s1.y += v1.y; s1.z += v1.z; s1.w += v1.w;
    }
    float inv = g_invcnt[bd];
    float4 o;
    o.x = (s0.x + s1.x) * inv; o.y = (s0.y + s1.y) * inv;
    o.z = (s0.z + s1.z) * inv; o.w = (s0.w + s1.w) * inv;
    ((float4*)g_pooled)[bd * S + t] = o;
}

// ---------------------------------------------------------------------------
// Kernel 2: U = pooled @ w1_half. 16-row pure-half tiles.
// Tiles: 0..7 = head pairs (batches 2i,2i+1, d0-7); 8..31 = flattened object
// rows in chunks of 16. Grid (32, 8) = 256 blocks, 128 threads
// (64 cols x 2 k-halves), smem As[k][16].
// ---------------------------------------------------------------------------
__device__ __forceinline__ int g1_row(int tile, int r) {
    if (tile < 8) return (tile * 2 + (r >> 3)) * 32 + (r & 7);
    int flat = (tile - 8) * 16 + r;
    return (flat / 24) * 32 + 8 + flat % 24;
}

__global__ __launch_bounds__(128) void gemm1_kernel(const float* __restrict__ w1)
{
    __shared__ float As[CC * 16];      // 48 KB, [k][r]
    __shared__ float red[64 * 16];     // 4 KB split-K partials
    int tile = blockIdx.x;             // 0..31
    int t = threadIdx.x;               // 0..127

    // Load As: thread handles (r = t&15, k4 strided). Conflict-light STS.
    {
        int r = t & 15;
        int row = g1_row(tile, r);
        const float4* src = (const float4*)&g_pooled[row * CC];
        for (int k4 = t >> 4; k4 < CC / 4; k4 += 8) {
            float4 v = __ldg(&src[k4]);
            As[(k4*4+0) * 16 + r] = v.x;
            As[(k4*4+1) * 16 + r] = v.y;
            As[(k4*4+2) * 16 + r] = v.z;
            As[(k4*4+3) * 16 + r] = v.w;
        }
    }
    __syncthreads();

    int half = t >> 6;                 // 0/1
    int lc   = t & 63;
    int col  = blockIdx.y * 64 + lc;
    int off  = (tile < 8) ? 0 : CC;
    const float* wp = w1 + off * H1 + col;
    int kb = half * (CC / 2);          // 0 or 384

    unsigned long long acc[8];
#pragma unroll
    for (int p = 0; p < 8; ++p) acc[p] = 0ULL;

    float wcur[16];
#pragma unroll
    for (int i = 0; i < 16; ++i) wcur[i] = __ldg(&wp[(kb + i) * H1]);

    for (int k0 = kb; k0 < kb + CC/2; k0 += 16) {
        float wnxt[16];
        int kn = (k0 + 16 < kb + CC/2) ? (k0 + 16) : kb;
#pragma unroll
        for (int i = 0; i < 16; ++i) wnxt[i] = __ldg(&wp[(kn + i) * H1]);
#pragma unroll
        for (int i = 0; i < 16; ++i) {
            unsigned long long wpk = bcast2(wcur[i]);
            const ulonglong2* ap = (const ulonglong2*)&As[(k0 + i) * 16];
            ulonglong2 q0 = ap[0], q1 = ap[1], q2 = ap[2], q3 = ap[3];
            fma2(acc[0], q0.x, wpk); fma2(acc[1], q0.y, wpk);
            fma2(acc[2], q1.x, wpk); fma2(acc[3], q1.y, wpk);
            fma2(acc[4], q2.x, wpk); fma2(acc[5], q2.y, wpk);
            fma2(acc[6], q3.x, wpk); fma2(acc[7], q3.y, wpk);
        }
#pragma unroll
        for (int i = 0; i < 16; ++i) wcur[i] = wnxt[i];
    }

    if (half == 1) {
#pragma unroll
        for (int p = 0; p < 8; ++p) {
            float2 f = unpack2(acc[p]);
            red[lc * 16 + 2*p]     = f.x;
            red[lc * 16 + 2*p + 1] = f.y;
        }
    }
    __syncthreads();
    if (half == 0) {
#pragma unroll
        for (int p = 0; p < 8; ++p) {
            float2 f = unpack2(acc[p]);
            g_U[g1_row(tile, 2*p)     * H1 + col] = f.x + red[lc * 16 + 2*p];
            g_U[g1_row(tile, 2*p + 1) * H1 + col] = f.y + red[lc * 16 + 2*p + 1];
        }
    }
}

// ---------------------------------------------------------------------------
// Kernel 3: fused pair-build + relu(x1) + GEMM2 + relu + GEMM3 + bias.
// 256 blocks of MT=12 pairs, 256 threads. 16-k double-buffered weight regs.
// ---------------------------------------------------------------------------
__global__ __launch_bounds__(256) void pair_mlp_kernel(
    const float* __restrict__ b1,
    const float* __restrict__ w2, const float* __restrict__ b2,
    const float* __restrict__ w3, const float* __restrict__ b3,
    float* __restrict__ out)
{
    __shared__ float x1t[H1 * MT];   // 24 KB, [n][m] (reused for GEMM3 partials)
    __shared__ float x2t[H2 * MT];   // 12 KB, [k][m]
    __shared__ int hr[MT], orr[MT];

    int g0 = blockIdx.x * MT;
    int t = threadIdx.x;

    if (t < MT) {
        int g = g0 + t;
        int b = g / NPAIR;
        int rem = g - b * NPAIR;
        int i = rem / NOO, j = rem - i * NOO;
        hr[t]  = g_hrow[b * NHH + i];
        orr[t] = g_orow[b * NOO + j];
    }
    __syncthreads();

    // Phase 1: x1t[n][m] = relu(U[hr][n] + U[orr][n] + b1[n]) -- float4 loads
    for (int idx = t; idx < MT * (H1/4); idx += 256) {
        int m = idx / (H1/4), n4 = idx - m * (H1/4);
        float4 uh = __ldg((const float4*)&g_U[hr[m]  * H1 + n4*4]);
        float4 uo = __ldg((const float4*)&g_U[orr[m] * H1 + n4*4]);
        float4 bb = __ldg((const float4*)&b1[n4*4]);
        x1t[(n4*4+0) * MT + m] = fmaxf(uh.x + uo.x + bb.x, 0.f);
        x1t[(n4*4+1) * MT + m] = fmaxf(uh.y + uo.y + bb.y, 0.f);
        x1t[(n4*4+2) * MT + m] = fmaxf(uh.z + uo.z + bb.z, 0.f);
        x1t[(n4*4+3) * MT + m] = fmaxf(uh.w + uo.w + bb.w, 0.f);
    }
    __syncthreads();

    // Phase 2: x2[m][t] = relu(x1 @ w2 + b2); thread t = output column
    {
        const float* wp = w2 + t;
        unsigned long long acc[6];
#pragma unroll
        for (int p = 0; p < 6; ++p) acc[p] = 0ULL;

        float wcur[16];
#pragma unroll
        for (int i = 0; i < 16; ++i) wcur[i] = __ldg(&wp[i * H2]);

        for (int k0 = 0; k0 < H1; k0 += 16) {
            float wnxt[16];
            int kn = (k0 + 16 < H1) ? (k0 + 16) : 0;
#pragma unroll
            for (int i = 0; i < 16; ++i) wnxt[i] = __ldg(&wp[(kn + i) * H2]);
#pragma unroll
            for (int i = 0; i < 16; ++i) {
                unsigned long long wpk = bcast2(wcur[i]);
                const ulonglong2* ap = (const ulonglong2*)&x1t[(k0 + i) * MT];
                ulonglong2 q0 = ap[0], q1 = ap[1], q2 = ap[2];
                fma2(acc[0], q0.x, wpk); fma2(acc[1], q0.y, wpk);
                fma2(acc[2], q1.x, wpk); fma2(acc[3], q1.y, wpk);
                fma2(acc[4], q2.x, wpk); fma2(acc[5], q2.y, wpk);
            }
#pragma unroll
            for (int i = 0; i < 16; ++i) wcur[i] = wnxt[i];
        }
        float bb = __ldg(&b2[t]);
#pragma unroll
        for (int p = 0; p < 6; ++p) {
            float2 f = unpack2(acc[p]);
            float2 s;
            s.x = fmaxf(f.x + bb, 0.f);
            s.y = fmaxf(f.y + bb, 0.f);
            *(float2*)&x2t[t * MT + 2*p] = s;
        }
    }
    __syncthreads();

    // Phase 3: out = x2 @ w3 + b3. 234 threads: split-K halves, smem reduce.
    float a3[MT];
    int half = (t >= H3) ? 1 : 0;
    int col  = t - half * H3;
    if (t < 2 * H3) {
        unsigned long long acc[6];
#pragma unroll
        for (int p = 0; p < 6; ++p) acc[p] = 0ULL;
        const float* wp3 = w3 + col;
        int kbeg = half * (H2/2);

        float wcur[16];
#pragma unroll
        for (int i = 0; i < 16; ++i) wcur[i] = __ldg(&wp3[(kbeg + i) * H3]);

        for (int k0 = kbeg; k0 < kbeg + H2/2; k0 += 16) {
            float wnxt[16];
            int kn = (k0 + 16 < kbeg + H2/2) ? (k0 + 16) : kbeg;
#pragma unroll
            for (int i = 0; i < 16; ++i) wnxt[i] = __ldg(&wp3[(kn + i) * H3]);
#pragma unroll
            for (int i = 0; i < 16; ++i) {
                unsigned long long wpk = bcast2(wcur[i]);
                const ulonglong2* ap = (const ulonglong2*)&x2t[(k0 + i) * MT];
                ulonglong2 q0 = ap[0], q1 = ap[1], q2 = ap[2];
                fma2(acc[0], q0.x, wpk); fma2(acc[1], q0.y, wpk);
                fma2(acc[2], q1.x, wpk); fma2(acc[3], q1.y, wpk);
                fma2(acc[4], q2.x, wpk); fma2(acc[5], q2.y, wpk);
            }
#pragma unroll
            for (int i = 0; i < 16; ++i) wcur[i] = wnxt[i];
        }
#pragma unroll
        for (int p = 0; p < 6; ++p) {
            float2 f = unpack2(acc[p]);
            a3[2*p] = f.x; a3[2*p + 1] = f.y;
        }
        if (half == 1) {
#pragma unroll
            for (int m = 0; m < MT; ++m) x1t[col * MT + m] = a3[m];
        }
    }
    __syncthreads();
    if (t < H3) {
        float bo = __ldg(&b3[t]);
#pragma unroll
        for (int m = 0; m < MT; ++m)
            out[(g0 + m) * H3 + t] = a3[m] + x1t[t * MT + m] + bo;
    }
}

// ---------------------------------------------------------------------------
extern "C" void kernel_launch(void* const* d_in, const int* in_sizes, int n_in,
                              void* d_out, int out_size)
{
    const float* features = (const float*)d_in[0];
    const float* boxes    = (const float*)d_in[1];
    const float* scores   = (const float*)d_in[2];
    const float* w1       = (const float*)d_in[3];
    const float* b1       = (const float*)d_in[4];
    const float* w2       = (const float*)d_in[5];
    const float* b2       = (const float*)d_in[6];
    const float* w3       = (const float*)d_in[7];
    const float* b3       = (const float*)d_in[8];
    float* out = (float*)d_out;

    pool_kernel<<<BB * DD * YSPLIT + 1, 192>>>(features, boxes, scores);
    reduce_kernel<<<BB * DD, 192>>>();
    dim3 g1(32, 8);
    gemm1_kernel<<<g1, 128>>>(w1);
    pair_mlp_kernel<<<(BB * NPAIR) / MT, 256>>>(b1, w2, b2, w3, b3, out);
}